// round 1
// baseline (speedup 1.0000x reference)
#include <cuda_runtime.h>

// out[row] = sum_l in[row*1024 + l] / (l+1),  rows = 4*8*4096 = 131072, L = 1024.
//
// Strategy: warp-per-row streaming reduction.
//  - Each lane handles columns l = lane*4 + j + 128*k (j=0..3, k=0..7) via float4.
//  - Reciprocal weights 1/(l+1) depend only on l: computed ONCE per warp into
//    registers (32 MUFU ops), reused across ROWS_PER_WARP rows -> kernel is
//    FFMA+LDG only, HBM-bound.
//  - 5-step shfl_xor reduction, lane 0 writes the scalar result.

static constexpr int L        = 1024;
static constexpr int ROWS     = 4 * 8 * 4096;   // 131072
static constexpr int RPW      = 8;              // rows per warp
static constexpr int THREADS  = 256;            // 8 warps per block

__global__ __launch_bounds__(THREADS)
void fractal_dim_kernel(const float* __restrict__ in, float* __restrict__ out) {
    const int lane      = threadIdx.x & 31;
    const int warp_glob = (blockIdx.x * THREADS + threadIdx.x) >> 5;

    // Per-lane reciprocal weights: l = lane*4 + j + 128*k
    float r[32];
    #pragma unroll
    for (int k = 0; k < 8; k++) {
        #pragma unroll
        for (int j = 0; j < 4; j++) {
            r[k * 4 + j] = 1.0f / (float)(lane * 4 + j + 128 * k + 1);
        }
    }

    int row0 = warp_glob * RPW;

    #pragma unroll
    for (int rr = 0; rr < RPW; rr++) {
        int row = row0 + rr;
        const float4* p = reinterpret_cast<const float4*>(in + (size_t)row * L) + lane;

        // Issue all 8 loads up front (MLP=8), then accumulate.
        float4 v[8];
        #pragma unroll
        for (int k = 0; k < 8; k++) {
            v[k] = p[k * 32];   // warp stride = 32 float4 = 128 floats
        }

        float s = 0.0f;
        #pragma unroll
        for (int k = 0; k < 8; k++) {
            s = fmaf(v[k].x, r[k * 4 + 0], s);
            s = fmaf(v[k].y, r[k * 4 + 1], s);
            s = fmaf(v[k].z, r[k * 4 + 2], s);
            s = fmaf(v[k].w, r[k * 4 + 3], s);
        }

        // Warp tree reduction
        #pragma unroll
        for (int off = 16; off > 0; off >>= 1) {
            s += __shfl_xor_sync(0xffffffffu, s, off);
        }

        if (lane == 0) {
            out[row] = s;
        }
    }
}

extern "C" void kernel_launch(void* const* d_in, const int* in_sizes, int n_in,
                              void* d_out, int out_size) {
    const float* in  = (const float*)d_in[0];
    float*       out = (float*)d_out;

    // ROWS / (warps_per_block * RPW) = 131072 / (8*8) = 2048 blocks
    const int blocks = ROWS / ((THREADS / 32) * RPW);
    fractal_dim_kernel<<<blocks, THREADS>>>(in, out);
}

// round 2
// speedup vs baseline: 1.0342x; 1.0342x over previous
#include <cuda_runtime.h>

// out[row] = sum_l in[row*1024 + l] / (l+1),  rows = 4*8*4096 = 131072, L = 1024.
//
// R2: weights moved from registers (32/thread) to shared memory (1024 floats,
// 4KB/block) -> regs ~70 -> ~48, occupancy 33.7% -> ~60%, more loads in flight.
// Data loads use __ldcs (read-once streaming). Two accumulators shorten the
// FFMA dependency chain.

static constexpr int L        = 1024;
static constexpr int ROWS     = 4 * 8 * 4096;   // 131072
static constexpr int RPW      = 8;              // rows per warp
static constexpr int THREADS  = 256;            // 8 warps per block

__global__ __launch_bounds__(THREADS, 5)
void fractal_dim_kernel(const float* __restrict__ in, float* __restrict__ out) {
    __shared__ float4 w4[L / 4];   // w4[i] = {1/(4i+1), 1/(4i+2), 1/(4i+3), 1/(4i+4)}

    const int t = threadIdx.x;

    // Each of the 256 threads computes 4 weights (one float4). 4 MUFU RCPs/thread.
    {
        float4 w;
        int base = t * 4;
        w.x = 1.0f / (float)(base + 1);
        w.y = 1.0f / (float)(base + 2);
        w.z = 1.0f / (float)(base + 3);
        w.w = 1.0f / (float)(base + 4);
        w4[t] = w;
    }
    __syncthreads();

    const int lane      = t & 31;
    const int warp_glob = (blockIdx.x * THREADS + t) >> 5;
    const int row0      = warp_glob * RPW;

    #pragma unroll
    for (int rr = 0; rr < RPW; rr++) {
        const int row = row0 + rr;
        const float4* p = reinterpret_cast<const float4*>(in + (size_t)row * L) + lane;

        // Front-batch all 8 loads (MLP=8 per warp), streaming hint (read-once).
        float4 v[8];
        #pragma unroll
        for (int k = 0; k < 8; k++) {
            v[k] = __ldcs(p + k * 32);   // warp stride = 32 float4 = 128 floats
        }

        float s0 = 0.0f, s1 = 0.0f;
        #pragma unroll
        for (int k = 0; k < 8; k++) {
            float4 w = w4[lane + 32 * k];
            s0 = fmaf(v[k].x, w.x, s0);
            s1 = fmaf(v[k].y, w.y, s1);
            s0 = fmaf(v[k].z, w.z, s0);
            s1 = fmaf(v[k].w, w.w, s1);
        }
        float s = s0 + s1;

        // Warp tree reduction
        #pragma unroll
        for (int off = 16; off > 0; off >>= 1) {
            s += __shfl_xor_sync(0xffffffffu, s, off);
        }

        if (lane == 0) {
            out[row] = s;
        }
    }
}

extern "C" void kernel_launch(void* const* d_in, const int* in_sizes, int n_in,
                              void* d_out, int out_size) {
    const float* in  = (const float*)d_in[0];
    float*       out = (float*)d_out;

    const int blocks = ROWS / ((THREADS / 32) * RPW);   // 2048
    fractal_dim_kernel<<<blocks, THREADS>>>(in, out);
}

// round 5
// speedup vs baseline: 1.1033x; 1.0668x over previous
#include <cuda_runtime.h>

// out[row] = sum_l in[row*1024 + l] / (l+1),  rows = 131072, L = 1024.
//
// R3: single-resident-wave launch. GRID = 152 SMs * 5 blocks/SM = 760 blocks,
// balanced static row split (blocks get 172-173 rows, warps ~21-22 contiguous
// rows). Removes the 2.7-wave quantization of R2 (last partial wave ran with
// too few in-flight loads to saturate the L1tex queue / HBM).
// Weights in smem, __ldcs streaming loads, 8 front-batched float4 per row.

static constexpr int L       = 1024;
static constexpr int ROWS    = 4 * 8 * 4096;   // 131072
static constexpr int THREADS = 256;            // 8 warps
static constexpr int GRID    = 152 * 5;        // 760: one full wave at 5 blocks/SM

__global__ __launch_bounds__(THREADS, 5)
void fractal_dim_kernel(const float* __restrict__ in, float* __restrict__ out) {
    __shared__ float4 w4[L / 4];   // w4[i] = {1/(4i+1), ..., 1/(4i+4)}

    const int t = threadIdx.x;
    {
        int base = t * 4;
        float4 w;
        w.x = 1.0f / (float)(base + 1);
        w.y = 1.0f / (float)(base + 2);
        w.z = 1.0f / (float)(base + 3);
        w.w = 1.0f / (float)(base + 4);
        w4[t] = w;
    }
    __syncthreads();

    const int lane = t & 31;
    const int wid  = t >> 5;

    // Balanced contiguous split: block range, then warp range within it.
    const int bstart = (int)((long long)blockIdx.x       * ROWS / GRID);
    const int bend   = (int)((long long)(blockIdx.x + 1) * ROWS / GRID);
    const int n      = bend - bstart;
    const int wstart = bstart + (int)((long long)wid       * n / 8);
    const int wend   = bstart + (int)((long long)(wid + 1) * n / 8);

    for (int row = wstart; row < wend; row++) {
        const float4* p = reinterpret_cast<const float4*>(in + (size_t)row * L) + lane;

        // Front-batch 8 loads (MLP=8 per warp), read-once streaming.
        float4 v[8];
        #pragma unroll
        for (int k = 0; k < 8; k++) {
            v[k] = __ldcs(p + k * 32);   // warp stride = 32 float4 = 128 floats
        }

        float s0 = 0.0f, s1 = 0.0f;
        #pragma unroll
        for (int k = 0; k < 8; k++) {
            float4 w = w4[lane + 32 * k];
            s0 = fmaf(v[k].x, w.x, s0);
            s1 = fmaf(v[k].y, w.y, s1);
            s0 = fmaf(v[k].z, w.z, s0);
            s1 = fmaf(v[k].w, w.w, s1);
        }
        float s = s0 + s1;

        #pragma unroll
        for (int off = 16; off > 0; off >>= 1) {
            s += __shfl_xor_sync(0xffffffffu, s, off);
        }

        if (lane == 0) {
            out[row] = s;
        }
    }
}

extern "C" void kernel_launch(void* const* d_in, const int* in_sizes, int n_in,
                              void* d_out, int out_size) {
    const float* in  = (const float*)d_in[0];
    float*       out = (float*)d_out;
    fractal_dim_kernel<<<GRID, THREADS>>>(in, out);
}